// round 11
// baseline (speedup 1.0000x reference)
#include <cuda_runtime.h>
#include <cuda_bf16.h>

#define NN 100000     // nodes
#define NE 1600000    // edges
#define NG 2048       // graphs
#define NFD 64        // node feature dim
#define DD 32         // hidden dim
#define BN_EPS 1e-5f
#define SCAN_B 512
#define NSB 196       // ceil(NN/SCAN_B)
#define NWB 1184      // blocks for gather kernels (8 warps each)
#define NMB 1563      // ceil(NN/64) blocks for MLP GEMM

// ---------------- scratch (zero at load; k_cleanup restores zeros each call) ----
__device__ int    g_rowptr[NN + 1];
__device__ int    g_rowcur[NN];        // histogram counts, then scatter cursors (0 at entry)
__device__ int    g_csrc[NE];          // CSR: src node ids grouped by dst
__device__ int    g_scan_ready;        // chained-scan turnstile (0 at entry)
__device__ int    g_running;           // chained-scan running total (0 at entry)
__device__ int    g_gstart[NG + 1];    // graph row boundaries (fully rewritten each call)
__device__ float  g_agg[NN * NFD];
__device__ float  g_ta[NN * DD];
__device__ float  g_tb[NN * DD];
__device__ double g_stats[5 * 64];     // per layer: [sum(32) | sumsq(32)] (0 at entry)
__device__ float  g_pooled[NG * DD];
__device__ float  g_s1[NG * 256];
__device__ float  g_z[NG * 256];
__device__ float  g_z1[NG * 1024];
__device__ float  g_z2[NG * 256];

// ---------------- CSR build: 3 launches ----------------
__global__ void k_hist(const int* __restrict__ ei) {
    int t = blockIdx.x * blockDim.x + threadIdx.x;
    if (t < NE) atomicAdd(&g_rowcur[ei[NE + t]], 1);
}

// single-pass chained exclusive scan: g_rowcur -> g_rowptr (+reset cursors)
__global__ void k_scanf() {
    __shared__ int sh[SCAN_B];
    __shared__ int sbase;
    int t = threadIdx.x, b = blockIdx.x;
    int i = b * SCAN_B + t;
    int v = (i < NN) ? g_rowcur[i] : 0;
    sh[t] = v; __syncthreads();
    for (int off = 1; off < SCAN_B; off <<= 1) {
        int a = (t >= off) ? sh[t - off] : 0;
        __syncthreads();
        sh[t] += a;
        __syncthreads();
    }
    int total = sh[SCAN_B - 1];
    if (t == 0) {
        while (atomicAdd(&g_scan_ready, 0) != b) { }   // wait my turn (all blocks wave-1 resident)
        sbase = g_running;
        g_running = sbase + total;
        __threadfence();
        atomicExch(&g_scan_ready, b + 1);
    }
    __syncthreads();
    if (i < NN) {
        int rp = sbase + sh[t] - v;
        g_rowptr[i] = rp;
        g_rowcur[i] = rp;
    }
    if (b == NSB - 1 && t == SCAN_B - 1) g_rowptr[NN] = NE;
}

__global__ void k_scatter(const int* __restrict__ ei) {
    int t = blockIdx.x * blockDim.x + threadIdx.x;
    if (t >= NE) return;
    int d = ei[NE + t];
    int pos = atomicAdd(&g_rowcur[d], 1);
    g_csrc[pos] = ei[t];
}

// ---------------- gather: layer 1 (x, 64 features), launch #4 => profiled ------
__global__ void k_gather1(const float* __restrict__ x) {
    int lane = threadIdx.x & 31;
    int warp   = (blockIdx.x * blockDim.x + threadIdx.x) >> 5;
    int nwarps = (gridDim.x * blockDim.x) >> 5;
    for (int r = warp; r < NN; r += nwarps) {
        float a0 = x[r * NFD + lane];
        float a1 = x[r * NFD + 32 + lane];
        int e = g_rowptr[r], end = g_rowptr[r + 1];
        for (; e + 4 <= end; e += 4) {
            int s0 = g_csrc[e], s1 = g_csrc[e + 1], s2 = g_csrc[e + 2], s3 = g_csrc[e + 3];
            float u0 = x[s0 * NFD + lane],      v0 = x[s0 * NFD + 32 + lane];
            float u1 = x[s1 * NFD + lane],      v1 = x[s1 * NFD + 32 + lane];
            float u2 = x[s2 * NFD + lane],      v2 = x[s2 * NFD + 32 + lane];
            float u3 = x[s3 * NFD + lane],      v3 = x[s3 * NFD + 32 + lane];
            a0 += (u0 + u1) + (u2 + u3);
            a1 += (v0 + v1) + (v2 + v3);
        }
        for (; e < end; e++) {
            int s = g_csrc[e];
            a0 += x[s * NFD + lane];
            a1 += x[s * NFD + 32 + lane];
        }
        g_agg[r * NFD + lane] = a0;
        g_agg[r * NFD + 32 + lane] = a1;
    }
}

// ---------------- gather: layers 2-5 (BN-relu folded) ----------------
__global__ void k_gather(const float* __restrict__ tin,
                         const float* __restrict__ bng, const float* __restrict__ bnb,
                         const double* __restrict__ stats_in) {
    __shared__ float ssc[DD], ssh[DD];
    if (threadIdx.x < DD) {
        double mu  = stats_in[threadIdx.x] / (double)NN;
        double var = stats_in[32 + threadIdx.x] / (double)NN - mu * mu;
        float sc = bng[threadIdx.x] * rsqrtf((float)var + BN_EPS);
        ssc[threadIdx.x] = sc;
        ssh[threadIdx.x] = bnb[threadIdx.x] - (float)mu * sc;
    }
    __syncthreads();
    int lane = threadIdx.x & 31;
    int warp   = (blockIdx.x * blockDim.x + threadIdx.x) >> 5;
    int nwarps = (gridDim.x * blockDim.x) >> 5;
    float sc = ssc[lane], sh = ssh[lane];
    for (int r = warp; r < NN; r += nwarps) {
        float a = fmaxf(fmaf(tin[r * DD + lane], sc, sh), 0.f);
        int e = g_rowptr[r], end = g_rowptr[r + 1];
        for (; e + 4 <= end; e += 4) {
            int s0 = g_csrc[e], s1 = g_csrc[e + 1], s2 = g_csrc[e + 2], s3 = g_csrc[e + 3];
            float v0 = fmaxf(fmaf(tin[s0 * DD + lane], sc, sh), 0.f);
            float v1 = fmaxf(fmaf(tin[s1 * DD + lane], sc, sh), 0.f);
            float v2 = fmaxf(fmaf(tin[s2 * DD + lane], sc, sh), 0.f);
            float v3 = fmaxf(fmaf(tin[s3 * DD + lane], sc, sh), 0.f);
            a += (v0 + v1) + (v2 + v3);
        }
        for (; e < end; e++) {
            int s = g_csrc[e];
            a += fmaxf(fmaf(tin[s * DD + lane], sc, sh), 0.f);
        }
        g_agg[r * DD + lane] = a;
    }
}

// ---------------- MLP GEMM: tout = relu(A@Wa+ba)@Wb+bb, + BN stat accumulation --
__global__ void k_mlp(const float* __restrict__ A, int K, float* __restrict__ tout,
                      const float* __restrict__ wa, const float* __restrict__ ba,
                      const float* __restrict__ wb, const float* __restrict__ bb,
                      double* __restrict__ stats_out) {
    __shared__ float As[64 * 65];
    __shared__ float W1[NFD * DD];
    __shared__ float W2[DD * DD];
    __shared__ float C1[64 * 33];
    __shared__ float sba[DD], sbb[DD];
    int tid = threadIdx.x;
    int r0 = blockIdx.x * 64;
    for (int i = tid; i < K * DD; i += 128) W1[i] = wa[i];
    for (int i = tid; i < DD * DD; i += 128) W2[i] = wb[i];
    if (tid < DD) { sba[tid] = ba[tid]; sbb[tid] = bb[tid]; }
    for (int i = tid; i < 64 * K; i += 128) {
        int row = i / K, k = i - row * K;
        int rr = r0 + row;
        As[row * 65 + k] = (rr < NN) ? A[(long)rr * K + k] : 0.f;
    }
    __syncthreads();

    int ty = tid >> 3, tx = tid & 7;
    float acc[4][4] = {};
    for (int k = 0; k < K; k++) {
        float a0 = As[(ty * 4 + 0) * 65 + k];
        float a1 = As[(ty * 4 + 1) * 65 + k];
        float a2 = As[(ty * 4 + 2) * 65 + k];
        float a3 = As[(ty * 4 + 3) * 65 + k];
        float w0 = W1[k * DD + tx * 4 + 0];
        float w1 = W1[k * DD + tx * 4 + 1];
        float w2 = W1[k * DD + tx * 4 + 2];
        float w3 = W1[k * DD + tx * 4 + 3];
        acc[0][0] = fmaf(a0, w0, acc[0][0]); acc[0][1] = fmaf(a0, w1, acc[0][1]);
        acc[0][2] = fmaf(a0, w2, acc[0][2]); acc[0][3] = fmaf(a0, w3, acc[0][3]);
        acc[1][0] = fmaf(a1, w0, acc[1][0]); acc[1][1] = fmaf(a1, w1, acc[1][1]);
        acc[1][2] = fmaf(a1, w2, acc[1][2]); acc[1][3] = fmaf(a1, w3, acc[1][3]);
        acc[2][0] = fmaf(a2, w0, acc[2][0]); acc[2][1] = fmaf(a2, w1, acc[2][1]);
        acc[2][2] = fmaf(a2, w2, acc[2][2]); acc[2][3] = fmaf(a2, w3, acc[2][3]);
        acc[3][0] = fmaf(a3, w0, acc[3][0]); acc[3][1] = fmaf(a3, w1, acc[3][1]);
        acc[3][2] = fmaf(a3, w2, acc[3][2]); acc[3][3] = fmaf(a3, w3, acc[3][3]);
    }
    #pragma unroll
    for (int i = 0; i < 4; i++)
        #pragma unroll
        for (int j = 0; j < 4; j++)
            C1[(ty * 4 + i) * 33 + tx * 4 + j] = fmaxf(acc[i][j] + sba[tx * 4 + j], 0.f);
    __syncthreads();

    float acc2[4][4] = {};
    #pragma unroll 8
    for (int k = 0; k < DD; k++) {
        float a0 = C1[(ty * 4 + 0) * 33 + k];
        float a1 = C1[(ty * 4 + 1) * 33 + k];
        float a2 = C1[(ty * 4 + 2) * 33 + k];
        float a3 = C1[(ty * 4 + 3) * 33 + k];
        float w0 = W2[k * DD + tx * 4 + 0];
        float w1 = W2[k * DD + tx * 4 + 1];
        float w2 = W2[k * DD + tx * 4 + 2];
        float w3 = W2[k * DD + tx * 4 + 3];
        acc2[0][0] = fmaf(a0, w0, acc2[0][0]); acc2[0][1] = fmaf(a0, w1, acc2[0][1]);
        acc2[0][2] = fmaf(a0, w2, acc2[0][2]); acc2[0][3] = fmaf(a0, w3, acc2[0][3]);
        acc2[1][0] = fmaf(a1, w0, acc2[1][0]); acc2[1][1] = fmaf(a1, w1, acc2[1][1]);
        acc2[1][2] = fmaf(a1, w2, acc2[1][2]); acc2[1][3] = fmaf(a1, w3, acc2[1][3]);
        acc2[2][0] = fmaf(a2, w0, acc2[2][0]); acc2[2][1] = fmaf(a2, w1, acc2[2][1]);
        acc2[2][2] = fmaf(a2, w2, acc2[2][2]); acc2[2][3] = fmaf(a2, w3, acc2[2][3]);
        acc2[3][0] = fmaf(a3, w0, acc2[3][0]); acc2[3][1] = fmaf(a3, w1, acc2[3][1]);
        acc2[3][2] = fmaf(a3, w2, acc2[3][2]); acc2[3][3] = fmaf(a3, w3, acc2[3][3]);
    }
    __syncthreads();
    #pragma unroll
    for (int i = 0; i < 4; i++) {
        int rr = r0 + ty * 4 + i;
        #pragma unroll
        for (int j = 0; j < 4; j++) {
            int c = tx * 4 + j;
            float v = acc2[i][j] + sbb[c];
            if (rr < NN) {
                tout[(long)rr * DD + c] = v;
                As[(ty * 4 + i) * 65 + c] = v;
            } else {
                As[(ty * 4 + i) * 65 + c] = 0.f;
            }
        }
    }
    __syncthreads();
    if (tid < DD) {
        float s = 0.f, q = 0.f;
        #pragma unroll 8
        for (int r = 0; r < 64; r++) {
            float v = As[r * 65 + tid];
            s += v;
            q = fmaf(v, v, q);
        }
        atomicAdd(&stats_out[tid], (double)s);
        atomicAdd(&stats_out[32 + tid], (double)q);
    }
}

// ---------------- graph boundaries from sorted batch ----------------
__global__ void k_gbounds(const int* __restrict__ batch) {
    int i = blockIdx.x * blockDim.x + threadIdx.x;
    if (i >= NN) return;
    int b0 = batch[i];
    int b1 = (i + 1 < NN) ? batch[i + 1] : NG;
    for (int g = b0 + 1; g <= b1; g++) g_gstart[g] = i + 1;
    if (i == 0)
        for (int g = 0; g <= b0; g++) g_gstart[g] = 0;
}

// ---------------- pooling: warp-per-graph segmented sum (no atomics) ----------
__global__ void k_pool(const float* __restrict__ tin,
                       const float* __restrict__ bng, const float* __restrict__ bnb,
                       const double* __restrict__ stats_in) {
    __shared__ float ssc[DD], ssh[DD];
    int tid = threadIdx.x;
    if (tid < DD) {
        double mu  = stats_in[tid] / (double)NN;
        double var = stats_in[32 + tid] / (double)NN - mu * mu;
        float sc = bng[tid] * rsqrtf((float)var + BN_EPS);
        ssc[tid] = sc;
        ssh[tid] = bnb[tid] - (float)mu * sc;
    }
    __syncthreads();
    int lane = tid & 31;
    int g = (blockIdx.x * blockDim.x + tid) >> 5;
    if (g >= NG) return;
    float sc = ssc[lane], sh = ssh[lane];
    int lo = g_gstart[g], hi = g_gstart[g + 1];
    float acc = 0.f;
    for (int r = lo; r < hi; r++)
        acc += fmaxf(fmaf(tin[r * DD + lane], sc, sh), 0.f);
    g_pooled[g * DD + lane] = acc;
}

// ---------------- head GEMM: 64x64 tile, 4x4 per thread ----------------
__global__ void k_gemm(const float* __restrict__ A, const float* __restrict__ W,
                       const float* __restrict__ bias, float* __restrict__ C,
                       int M, int K, int Nc, int ldc, int do_relu) {
    const int BM = 64, BN = 64, BK = 16;
    __shared__ float As[BK][BM + 1];
    __shared__ float Ws[BK][BN];
    int tx = threadIdx.x & 15, ty = threadIdx.x >> 4;
    int row0 = blockIdx.y * BM, col0 = blockIdx.x * BN;
    float acc[4][4] = {};
    for (int k0 = 0; k0 < K; k0 += BK) {
        for (int i = threadIdx.x; i < BM * BK; i += 256) {
            int m = i >> 4, kk = i & 15;
            As[kk][m] = A[(long)(row0 + m) * K + k0 + kk];
        }
        for (int i = threadIdx.x; i < BK * BN; i += 256) {
            int kk = i >> 6, n = i & 63;
            Ws[kk][n] = W[(long)(k0 + kk) * Nc + col0 + n];
        }
        __syncthreads();
        #pragma unroll
        for (int kk = 0; kk < BK; kk++) {
            float a[4], w[4];
            #pragma unroll
            for (int i = 0; i < 4; i++) a[i] = As[kk][ty * 4 + i];
            #pragma unroll
            for (int j = 0; j < 4; j++) w[j] = Ws[kk][tx * 4 + j];
            #pragma unroll
            for (int i = 0; i < 4; i++)
                #pragma unroll
                for (int j = 0; j < 4; j++) acc[i][j] = fmaf(a[i], w[j], acc[i][j]);
        }
        __syncthreads();
    }
    #pragma unroll
    for (int i = 0; i < 4; i++) {
        int r = row0 + ty * 4 + i;
        #pragma unroll
        for (int j = 0; j < 4; j++) {
            int c = col0 + tx * 4 + j;
            float v = acc[i][j] + bias[c];
            if (do_relu) v = fmaxf(v, 0.f);
            C[(long)r * ldc + c] = v;
        }
    }
}

__global__ void k_out(const float* __restrict__ ow, const float* __restrict__ ob,
                      float* __restrict__ out) {
    int warp = (blockIdx.x * blockDim.x + threadIdx.x) >> 5;
    int lane = threadIdx.x & 31;
    if (warp >= NG) return;
    float acc = 0.f;
    #pragma unroll
    for (int k = lane; k < 256; k += 32)
        acc = fmaf(g_z2[warp * 256 + k], ow[k], acc);
    #pragma unroll
    for (int o = 16; o; o >>= 1) acc += __shfl_down_sync(0xffffffffu, acc, o);
    if (lane == 0) out[warp] = acc + ob[0];
}

// restore load-time-zero state for the next replay
__global__ void k_cleanup() {
    int i = blockIdx.x * blockDim.x + threadIdx.x;
    if (i < NN) g_rowcur[i] = 0;
    if (i < 5 * 64) g_stats[i] = 0.0;
    if (i == 0) { g_scan_ready = 0; g_running = 0; }
}

// ---------------- launch ----------------
extern "C" void kernel_launch(void* const* d_in, const int* in_sizes, int n_in,
                              void* d_out, int out_size) {
    const float* x     = (const float*)d_in[0];
    const int*   ei    = (const int*)d_in[1];
    const int*   batch = (const int*)d_in[2];
    const float* sf    = (const float*)d_in[3];
    const float* w1a   = (const float*)d_in[4];
    const float* b1a   = (const float*)d_in[5];
    const float* ws_a  = (const float*)d_in[6];
    const float* bs_a  = (const float*)d_in[7];
    const float* ws_b  = (const float*)d_in[8];
    const float* bs_b  = (const float*)d_in[9];
    const float* bn_g  = (const float*)d_in[10];
    const float* bn_b  = (const float*)d_in[11];
    const float* fcg_w = (const float*)d_in[12];
    const float* fcg_b = (const float*)d_in[13];
    const float* fs1_w = (const float*)d_in[14];
    const float* fs1_b = (const float*)d_in[15];
    const float* fs2_w = (const float*)d_in[16];
    const float* fs2_b = (const float*)d_in[17];
    const float* fc1_w = (const float*)d_in[18];
    const float* fc1_b = (const float*)d_in[19];
    const float* fc2_w = (const float*)d_in[20];
    const float* fc2_b = (const float*)d_in[21];
    const float* out_w = (const float*)d_in[22];
    const float* out_b = (const float*)d_in[23];
    float* out = (float*)d_out;

    float *p_agg, *p_ta, *p_tb, *p_pooled, *p_s1, *p_z, *p_z1, *p_z2;
    double* p_stats;
    cudaGetSymbolAddress((void**)&p_agg, g_agg);
    cudaGetSymbolAddress((void**)&p_ta, g_ta);
    cudaGetSymbolAddress((void**)&p_tb, g_tb);
    cudaGetSymbolAddress((void**)&p_stats, g_stats);
    cudaGetSymbolAddress((void**)&p_pooled, g_pooled);
    cudaGetSymbolAddress((void**)&p_s1, g_s1);
    cudaGetSymbolAddress((void**)&p_z, g_z);
    cudaGetSymbolAddress((void**)&p_z1, g_z1);
    cudaGetSymbolAddress((void**)&p_z2, g_z2);

    const int TB = 256;

    // CSR build: exactly 3 launches -> k_gather1 is launch #4 (profiled by ncu)
    k_hist<<<(NE + TB - 1) / TB, TB>>>(ei);
    k_scanf<<<NSB, SCAN_B>>>();
    k_scatter<<<(NE + TB - 1) / TB, TB>>>(ei);

    // layer 1
    k_gather1<<<NWB, TB>>>(x);
    k_mlp<<<NMB, 128>>>(p_agg, NFD, p_ta, w1a, b1a, ws_b, bs_b, p_stats);

    // layers 2-5
    float* bufs[2] = { p_ta, p_tb };
    for (int i = 1; i < 5; i++) {
        const float* tin = bufs[(i + 1) & 1];
        float* tout = bufs[i & 1];
        k_gather<<<NWB, TB>>>(tin, bn_g + (i - 1) * DD, bn_b + (i - 1) * DD,
                              p_stats + (i - 1) * 64);
        k_mlp<<<NMB, 128>>>(p_agg, DD, tout,
                            ws_a + (i - 1) * DD * DD, bs_a + (i - 1) * DD,
                            ws_b + i * DD * DD, bs_b + i * DD,
                            p_stats + i * 64);
    }
    float* last = bufs[4 & 1];  // p_ta holds layer-5 pre-BN output

    // pool: boundaries + warp-per-graph segmented sum (BN folded)
    k_gbounds<<<(NN + TB - 1) / TB, TB>>>(batch);
    k_pool<<<(NG * 32 + TB - 1) / TB, TB>>>(last, bn_g + 4 * DD, bn_b + 4 * DD,
                                            p_stats + 4 * 64);

    // head
    k_gemm<<<dim3(128 / 64, NG / 64), 256>>>(p_pooled, fcg_w, fcg_b, p_z,
                                             NG, DD, 128, 256, 1);
    k_gemm<<<dim3(256 / 64, NG / 64), 256>>>(sf, fs1_w, fs1_b, p_s1,
                                             NG, 512, 256, 256, 1);
    k_gemm<<<dim3(128 / 64, NG / 64), 256>>>(p_s1, fs2_w, fs2_b, p_z + 128,
                                             NG, 256, 128, 256, 1);
    k_gemm<<<dim3(1024 / 64, NG / 64), 256>>>(p_z, fc1_w, fc1_b, p_z1,
                                              NG, 256, 1024, 1024, 1);
    k_gemm<<<dim3(256 / 64, NG / 64), 256>>>(p_z1, fc2_w, fc2_b, p_z2,
                                             NG, 1024, 256, 256, 1);
    k_out<<<(NG * 32 + TB - 1) / TB, TB>>>(out_w, out_b, out);

    // restore zero state for next replay
    k_cleanup<<<(NN + TB - 1) / TB, TB>>>();
}

// round 14
// speedup vs baseline: 1.7717x; 1.7717x over previous
#include <cuda_runtime.h>
#include <cuda_bf16.h>

#define NN 100000     // nodes
#define NE 1600000    // edges
#define NG 2048       // graphs
#define NFD 64        // node feature dim
#define DD 32         // hidden dim
#define BN_EPS 1e-5f
#define SCAN_B 512
#define NSB 196       // ceil(NN/SCAN_B)
#define NWB 1184      // blocks for gather kernels (8 warps each)
#define NMB 1563      // ceil(NN/64) blocks for MLP GEMM

// ---------------- scratch (zero at load; k_cleanup restores zeros each call) ----
__device__ int    g_rowptr[NN + 1];
__device__ int    g_rowcur[NN];        // histogram counts, then scatter cursors (0 at entry)
__device__ int    g_csrc[NE];          // CSR: src node ids grouped by dst
__device__ int    g_bsum[256];
__device__ int    g_gstart[NG + 1];    // graph row boundaries (fully rewritten each call)
__device__ float  g_agg[NN * NFD];
__device__ float  g_ta[NN * DD];
__device__ float  g_tb[NN * DD];
__device__ double g_stats[5 * 64];     // per layer: [sum(32) | sumsq(32)] (0 at entry)
__device__ float  g_pooled[NG * DD];
__device__ float  g_s1[NG * 256];
__device__ float  g_z[NG * 256];
__device__ float  g_z1[NG * 1024];
__device__ float  g_z2[NG * 256];

// ---------------- CSR build: 5 launches ----------------
__global__ void k_hist(const int* __restrict__ ei) {
    int t = blockIdx.x * blockDim.x + threadIdx.x;
    if (t < NE) atomicAdd(&g_rowcur[ei[NE + t]], 1);
}

__global__ void k_scan1() {
    __shared__ int sh[SCAN_B];
    int t = threadIdx.x, b = blockIdx.x;
    int i = b * SCAN_B + t;
    int v = (i < NN) ? g_rowcur[i] : 0;
    sh[t] = v; __syncthreads();
    for (int off = 1; off < SCAN_B; off <<= 1) {
        int a = (t >= off) ? sh[t - off] : 0;
        __syncthreads();
        sh[t] += a;
        __syncthreads();
    }
    if (i < NN) g_rowptr[i] = sh[t] - v;
    if (t == SCAN_B - 1) g_bsum[b] = sh[t];
}

__global__ void k_scan2() {
    __shared__ int sh[256];
    int t = threadIdx.x;
    int v = (t < NSB) ? g_bsum[t] : 0;
    sh[t] = v; __syncthreads();
    for (int off = 1; off < 256; off <<= 1) {
        int a = (t >= off) ? sh[t - off] : 0;
        __syncthreads();
        sh[t] += a;
        __syncthreads();
    }
    if (t < NSB) g_bsum[t] = sh[t] - v;
}

__global__ void k_scan3() {
    int i = blockIdx.x * blockDim.x + threadIdx.x;
    if (i < NN) {
        int rp = g_rowptr[i] + g_bsum[i >> 9];
        g_rowptr[i] = rp;
        g_rowcur[i] = rp;
    }
    if (i == 0) g_rowptr[NN] = NE;
}

__global__ void k_scatter(const int* __restrict__ ei) {
    int t = blockIdx.x * blockDim.x + threadIdx.x;
    if (t >= NE) return;
    int d = ei[NE + t];
    int pos = atomicAdd(&g_rowcur[d], 1);
    g_csrc[pos] = ei[t];
}

// ---------------- gather: layer 1 (x, 64 features) ----------------
__global__ void k_gather1(const float* __restrict__ x) {
    int lane = threadIdx.x & 31;
    int warp   = (blockIdx.x * blockDim.x + threadIdx.x) >> 5;
    int nwarps = (gridDim.x * blockDim.x) >> 5;
    for (int r = warp; r < NN; r += nwarps) {
        float a0 = x[r * NFD + lane];
        float a1 = x[r * NFD + 32 + lane];
        int e = g_rowptr[r], end = g_rowptr[r + 1];
        for (; e + 4 <= end; e += 4) {
            int s0 = g_csrc[e], s1 = g_csrc[e + 1], s2 = g_csrc[e + 2], s3 = g_csrc[e + 3];
            float u0 = x[s0 * NFD + lane],      v0 = x[s0 * NFD + 32 + lane];
            float u1 = x[s1 * NFD + lane],      v1 = x[s1 * NFD + 32 + lane];
            float u2 = x[s2 * NFD + lane],      v2 = x[s2 * NFD + 32 + lane];
            float u3 = x[s3 * NFD + lane],      v3 = x[s3 * NFD + 32 + lane];
            a0 += (u0 + u1) + (u2 + u3);
            a1 += (v0 + v1) + (v2 + v3);
        }
        for (; e < end; e++) {
            int s = g_csrc[e];
            a0 += x[s * NFD + lane];
            a1 += x[s * NFD + 32 + lane];
        }
        g_agg[r * NFD + lane] = a0;
        g_agg[r * NFD + 32 + lane] = a1;
    }
}

// ---------------- gather: layers 2-5 (BN-relu folded) ----------------
__global__ void k_gather(const float* __restrict__ tin,
                         const float* __restrict__ bng, const float* __restrict__ bnb,
                         const double* __restrict__ stats_in) {
    __shared__ float ssc[DD], ssh[DD];
    if (threadIdx.x < DD) {
        double mu  = stats_in[threadIdx.x] / (double)NN;
        double var = stats_in[32 + threadIdx.x] / (double)NN - mu * mu;
        float sc = bng[threadIdx.x] * rsqrtf((float)var + BN_EPS);
        ssc[threadIdx.x] = sc;
        ssh[threadIdx.x] = bnb[threadIdx.x] - (float)mu * sc;
    }
    __syncthreads();
    int lane = threadIdx.x & 31;
    int warp   = (blockIdx.x * blockDim.x + threadIdx.x) >> 5;
    int nwarps = (gridDim.x * blockDim.x) >> 5;
    float sc = ssc[lane], sh = ssh[lane];
    for (int r = warp; r < NN; r += nwarps) {
        float a = fmaxf(fmaf(tin[r * DD + lane], sc, sh), 0.f);
        int e = g_rowptr[r], end = g_rowptr[r + 1];
        for (; e + 4 <= end; e += 4) {
            int s0 = g_csrc[e], s1 = g_csrc[e + 1], s2 = g_csrc[e + 2], s3 = g_csrc[e + 3];
            float v0 = fmaxf(fmaf(tin[s0 * DD + lane], sc, sh), 0.f);
            float v1 = fmaxf(fmaf(tin[s1 * DD + lane], sc, sh), 0.f);
            float v2 = fmaxf(fmaf(tin[s2 * DD + lane], sc, sh), 0.f);
            float v3 = fmaxf(fmaf(tin[s3 * DD + lane], sc, sh), 0.f);
            a += (v0 + v1) + (v2 + v3);
        }
        for (; e < end; e++) {
            int s = g_csrc[e];
            a += fmaxf(fmaf(tin[s * DD + lane], sc, sh), 0.f);
        }
        g_agg[r * DD + lane] = a;
    }
}

// ---------------- MLP GEMM: tout = relu(A@Wa+ba)@Wb+bb, + BN stat accumulation --
// A: [NN, K] (K=64 layer1, 32 otherwise), 64-row tile per block, 128 threads.
__global__ void k_mlp(const float* __restrict__ A, int K, float* __restrict__ tout,
                      const float* __restrict__ wa, const float* __restrict__ ba,
                      const float* __restrict__ wb, const float* __restrict__ bb,
                      double* __restrict__ stats_out) {
    __shared__ float As[64 * 65];
    __shared__ float W1[NFD * DD];
    __shared__ float W2[DD * DD];
    __shared__ float C1[64 * 33];
    __shared__ float sba[DD], sbb[DD];
    int tid = threadIdx.x;
    int r0 = blockIdx.x * 64;
    // float4 weight fills
    for (int i = tid; i < (K * DD) / 4; i += 128)
        reinterpret_cast<float4*>(W1)[i] = reinterpret_cast<const float4*>(wa)[i];
    for (int i = tid; i < (DD * DD) / 4; i += 128)
        reinterpret_cast<float4*>(W2)[i] = reinterpret_cast<const float4*>(wb)[i];
    if (tid < DD) { sba[tid] = ba[tid]; sbb[tid] = bb[tid]; }
    // float4 A-tile fill (scalar stores into padded smem)
    {
        int kq = K >> 2;                    // float4s per row
        for (int i = tid; i < 64 * kq; i += 128) {
            int row = i / kq, q = i - row * kq;
            int rr = r0 + row;
            float4 v;
            if (rr < NN) v = reinterpret_cast<const float4*>(A + (long)rr * K)[q];
            else         v = make_float4(0.f, 0.f, 0.f, 0.f);
            float* dst = &As[row * 65 + q * 4];
            dst[0] = v.x; dst[1] = v.y; dst[2] = v.z; dst[3] = v.w;
        }
    }
    __syncthreads();

    int ty = tid >> 3, tx = tid & 7;
    float acc[4][4] = {};
    for (int k = 0; k < K; k++) {
        float a0 = As[(ty * 4 + 0) * 65 + k];
        float a1 = As[(ty * 4 + 1) * 65 + k];
        float a2 = As[(ty * 4 + 2) * 65 + k];
        float a3 = As[(ty * 4 + 3) * 65 + k];
        float w0 = W1[k * DD + tx * 4 + 0];
        float w1 = W1[k * DD + tx * 4 + 1];
        float w2 = W1[k * DD + tx * 4 + 2];
        float w3 = W1[k * DD + tx * 4 + 3];
        acc[0][0] = fmaf(a0, w0, acc[0][0]); acc[0][1] = fmaf(a0, w1, acc[0][1]);
        acc[0][2] = fmaf(a0, w2, acc[0][2]); acc[0][3] = fmaf(a0, w3, acc[0][3]);
        acc[1][0] = fmaf(a1, w0, acc[1][0]); acc[1][1] = fmaf(a1, w1, acc[1][1]);
        acc[1][2] = fmaf(a1, w2, acc[1][2]); acc[1][3] = fmaf(a1, w3, acc[1][3]);
        acc[2][0] = fmaf(a2, w0, acc[2][0]); acc[2][1] = fmaf(a2, w1, acc[2][1]);
        acc[2][2] = fmaf(a2, w2, acc[2][2]); acc[2][3] = fmaf(a2, w3, acc[2][3]);
        acc[3][0] = fmaf(a3, w0, acc[3][0]); acc[3][1] = fmaf(a3, w1, acc[3][1]);
        acc[3][2] = fmaf(a3, w2, acc[3][2]); acc[3][3] = fmaf(a3, w3, acc[3][3]);
    }
    #pragma unroll
    for (int i = 0; i < 4; i++)
        #pragma unroll
        for (int j = 0; j < 4; j++)
            C1[(ty * 4 + i) * 33 + tx * 4 + j] = fmaxf(acc[i][j] + sba[tx * 4 + j], 0.f);
    __syncthreads();

    float acc2[4][4] = {};
    #pragma unroll 8
    for (int k = 0; k < DD; k++) {
        float a0 = C1[(ty * 4 + 0) * 33 + k];
        float a1 = C1[(ty * 4 + 1) * 33 + k];
        float a2 = C1[(ty * 4 + 2) * 33 + k];
        float a3 = C1[(ty * 4 + 3) * 33 + k];
        float w0 = W2[k * DD + tx * 4 + 0];
        float w1 = W2[k * DD + tx * 4 + 1];
        float w2 = W2[k * DD + tx * 4 + 2];
        float w3 = W2[k * DD + tx * 4 + 3];
        acc2[0][0] = fmaf(a0, w0, acc2[0][0]); acc2[0][1] = fmaf(a0, w1, acc2[0][1]);
        acc2[0][2] = fmaf(a0, w2, acc2[0][2]); acc2[0][3] = fmaf(a0, w3, acc2[0][3]);
        acc2[1][0] = fmaf(a1, w0, acc2[1][0]); acc2[1][1] = fmaf(a1, w1, acc2[1][1]);
        acc2[1][2] = fmaf(a1, w2, acc2[1][2]); acc2[1][3] = fmaf(a1, w3, acc2[1][3]);
        acc2[2][0] = fmaf(a2, w0, acc2[2][0]); acc2[2][1] = fmaf(a2, w1, acc2[2][1]);
        acc2[2][2] = fmaf(a2, w2, acc2[2][2]); acc2[2][3] = fmaf(a2, w3, acc2[2][3]);
        acc2[3][0] = fmaf(a3, w0, acc2[3][0]); acc2[3][1] = fmaf(a3, w1, acc2[3][1]);
        acc2[3][2] = fmaf(a3, w2, acc2[3][2]); acc2[3][3] = fmaf(a3, w3, acc2[3][3]);
    }
    __syncthreads();
    #pragma unroll
    for (int i = 0; i < 4; i++) {
        int rr = r0 + ty * 4 + i;
        #pragma unroll
        for (int j = 0; j < 4; j++) {
            int c = tx * 4 + j;
            float v = acc2[i][j] + sbb[c];
            if (rr < NN) {
                tout[(long)rr * DD + c] = v;
                As[(ty * 4 + i) * 65 + c] = v;
            } else {
                As[(ty * 4 + i) * 65 + c] = 0.f;
            }
        }
    }
    __syncthreads();
    if (tid < DD) {
        float s = 0.f, q = 0.f;
        #pragma unroll 8
        for (int r = 0; r < 64; r++) {
            float v = As[r * 65 + tid];
            s += v;
            q = fmaf(v, v, q);
        }
        atomicAdd(&stats_out[tid], (double)s);
        atomicAdd(&stats_out[32 + tid], (double)q);
    }
}

// ---------------- graph boundaries from sorted batch ----------------
__global__ void k_gbounds(const int* __restrict__ batch) {
    int i = blockIdx.x * blockDim.x + threadIdx.x;
    if (i >= NN) return;
    int b0 = batch[i];
    int b1 = (i + 1 < NN) ? batch[i + 1] : NG;
    for (int g = b0 + 1; g <= b1; g++) g_gstart[g] = i + 1;
    if (i == 0)
        for (int g = 0; g <= b0; g++) g_gstart[g] = 0;
}

// ---------------- pooling: warp-per-graph segmented sum (no atomics) ----------
__global__ void k_pool(const float* __restrict__ tin,
                       const float* __restrict__ bng, const float* __restrict__ bnb,
                       const double* __restrict__ stats_in) {
    __shared__ float ssc[DD], ssh[DD];
    int tid = threadIdx.x;
    if (tid < DD) {
        double mu  = stats_in[tid] / (double)NN;
        double var = stats_in[32 + tid] / (double)NN - mu * mu;
        float sc = bng[tid] * rsqrtf((float)var + BN_EPS);
        ssc[tid] = sc;
        ssh[tid] = bnb[tid] - (float)mu * sc;
    }
    __syncthreads();
    int lane = tid & 31;
    int g = (blockIdx.x * blockDim.x + tid) >> 5;
    if (g >= NG) return;
    float sc = ssc[lane], sh = ssh[lane];
    int lo = g_gstart[g], hi = g_gstart[g + 1];
    float acc = 0.f;
    for (int r = lo; r < hi; r++)
        acc += fmaxf(fmaf(tin[r * DD + lane], sc, sh), 0.f);
    g_pooled[g * DD + lane] = acc;
}

// ---------------- head GEMM: 64x64 tile, BK=32, float4 loads ----------------
__global__ void k_gemm(const float* __restrict__ A, const float* __restrict__ W,
                       const float* __restrict__ bias, float* __restrict__ C,
                       int M, int K, int Nc, int ldc, int do_relu) {
    const int BM = 64, BN = 64, BK = 32;
    __shared__ float As[BK][BM + 1];
    __shared__ float Ws[BK][BN];
    int tx = threadIdx.x & 15, ty = threadIdx.x >> 4;
    int row0 = blockIdx.y * BM, col0 = blockIdx.x * BN;
    float acc[4][4] = {};
    for (int k0 = 0; k0 < K; k0 += BK) {
        // A tile: 64 rows x 32 k = 512 float4s
        for (int i = threadIdx.x; i < BM * (BK / 4); i += 256) {
            int m = i >> 3, q = i & 7;
            float4 v = reinterpret_cast<const float4*>(A + (long)(row0 + m) * K + k0)[q];
            As[q * 4 + 0][m] = v.x;
            As[q * 4 + 1][m] = v.y;
            As[q * 4 + 2][m] = v.z;
            As[q * 4 + 3][m] = v.w;
        }
        // W tile: 32 k x 64 n = 512 float4s (direct float4 stores)
        for (int i = threadIdx.x; i < BK * (BN / 4); i += 256) {
            int kk = i >> 4, q = i & 15;
            float4 v = reinterpret_cast<const float4*>(W + (long)(k0 + kk) * Nc + col0)[q];
            reinterpret_cast<float4*>(&Ws[kk][0])[q] = v;
        }
        __syncthreads();
        #pragma unroll
        for (int kk = 0; kk < BK; kk++) {
            float a[4], w[4];
            #pragma unroll
            for (int i = 0; i < 4; i++) a[i] = As[kk][ty * 4 + i];
            #pragma unroll
            for (int j = 0; j < 4; j++) w[j] = Ws[kk][tx * 4 + j];
            #pragma unroll
            for (int i = 0; i < 4; i++)
                #pragma unroll
                for (int j = 0; j < 4; j++) acc[i][j] = fmaf(a[i], w[j], acc[i][j]);
        }
        __syncthreads();
    }
    #pragma unroll
    for (int i = 0; i < 4; i++) {
        int r = row0 + ty * 4 + i;
        #pragma unroll
        for (int j = 0; j < 4; j++) {
            int c = col0 + tx * 4 + j;
            float v = acc[i][j] + bias[c];
            if (do_relu) v = fmaxf(v, 0.f);
            C[(long)r * ldc + c] = v;
        }
    }
}

__global__ void k_out(const float* __restrict__ ow, const float* __restrict__ ob,
                      float* __restrict__ out) {
    int warp = (blockIdx.x * blockDim.x + threadIdx.x) >> 5;
    int lane = threadIdx.x & 31;
    if (warp >= NG) return;
    float acc = 0.f;
    #pragma unroll
    for (int k = lane; k < 256; k += 32)
        acc = fmaf(g_z2[warp * 256 + k], ow[k], acc);
    #pragma unroll
    for (int o = 16; o; o >>= 1) acc += __shfl_down_sync(0xffffffffu, acc, o);
    if (lane == 0) out[warp] = acc + ob[0];
}

// restore load-time-zero state for the next replay
__global__ void k_cleanup() {
    int i = blockIdx.x * blockDim.x + threadIdx.x;
    if (i < NN) g_rowcur[i] = 0;
    if (i < 5 * 64) g_stats[i] = 0.0;
}

// ---------------- launch ----------------
extern "C" void kernel_launch(void* const* d_in, const int* in_sizes, int n_in,
                              void* d_out, int out_size) {
    const float* x     = (const float*)d_in[0];
    const int*   ei    = (const int*)d_in[1];
    const int*   batch = (const int*)d_in[2];
    const float* sf    = (const float*)d_in[3];
    const float* w1a   = (const float*)d_in[4];
    const float* b1a   = (const float*)d_in[5];
    const float* ws_a  = (const float*)d_in[6];
    const float* bs_a  = (const float*)d_in[7];
    const float* ws_b  = (const float*)d_in[8];
    const float* bs_b  = (const float*)d_in[9];
    const float* bn_g  = (const float*)d_in[10];
    const float* bn_b  = (const float*)d_in[11];
    const float* fcg_w = (const float*)d_in[12];
    const float* fcg_b = (const float*)d_in[13];
    const float* fs1_w = (const float*)d_in[14];
    const float* fs1_b = (const float*)d_in[15];
    const float* fs2_w = (const float*)d_in[16];
    const float* fs2_b = (const float*)d_in[17];
    const float* fc1_w = (const float*)d_in[18];
    const float* fc1_b = (const float*)d_in[19];
    const float* fc2_w = (const float*)d_in[20];
    const float* fc2_b = (const float*)d_in[21];
    const float* out_w = (const float*)d_in[22];
    const float* out_b = (const float*)d_in[23];
    float* out = (float*)d_out;

    float *p_agg, *p_ta, *p_tb, *p_pooled, *p_s1, *p_z, *p_z1, *p_z2;
    double* p_stats;
    cudaGetSymbolAddress((void**)&p_agg, g_agg);
    cudaGetSymbolAddress((void**)&p_ta, g_ta);
    cudaGetSymbolAddress((void**)&p_tb, g_tb);
    cudaGetSymbolAddress((void**)&p_stats, g_stats);
    cudaGetSymbolAddress((void**)&p_pooled, g_pooled);
    cudaGetSymbolAddress((void**)&p_s1, g_s1);
    cudaGetSymbolAddress((void**)&p_z, g_z);
    cudaGetSymbolAddress((void**)&p_z1, g_z1);
    cudaGetSymbolAddress((void**)&p_z2, g_z2);

    const int TB = 256;

    // CSR build (multi-block scan — measured-fast R10 config)
    k_hist<<<(NE + TB - 1) / TB, TB>>>(ei);
    k_scan1<<<NSB, SCAN_B>>>();
    k_scan2<<<1, 256>>>();
    k_scan3<<<(NN + TB - 1) / TB, TB>>>();
    k_scatter<<<(NE + TB - 1) / TB, TB>>>(ei);

    // layer 1
    k_gather1<<<NWB, TB>>>(x);
    k_mlp<<<NMB, 128>>>(p_agg, NFD, p_ta, w1a, b1a, ws_b, bs_b, p_stats);

    // layers 2-5
    float* bufs[2] = { p_ta, p_tb };
    for (int i = 1; i < 5; i++) {
        const float* tin = bufs[(i + 1) & 1];
        float* tout = bufs[i & 1];
        k_gather<<<NWB, TB>>>(tin, bn_g + (i - 1) * DD, bn_b + (i - 1) * DD,
                              p_stats + (i - 1) * 64);
        k_mlp<<<NMB, 128>>>(p_agg, DD, tout,
                            ws_a + (i - 1) * DD * DD, bs_a + (i - 1) * DD,
                            ws_b + i * DD * DD, bs_b + i * DD,
                            p_stats + i * 64);
    }
    float* last = bufs[4 & 1];  // p_ta holds layer-5 pre-BN output

    // pool: boundaries + warp-per-graph segmented sum (BN folded)
    k_gbounds<<<(NN + TB - 1) / TB, TB>>>(batch);
    k_pool<<<(NG * 32 + TB - 1) / TB, TB>>>(last, bn_g + 4 * DD, bn_b + 4 * DD,
                                            p_stats + 4 * 64);

    // head
    k_gemm<<<dim3(128 / 64, NG / 64), 256>>>(p_pooled, fcg_w, fcg_b, p_z,
                                             NG, DD, 128, 256, 1);
    k_gemm<<<dim3(256 / 64, NG / 64), 256>>>(sf, fs1_w, fs1_b, p_s1,
                                             NG, 512, 256, 256, 1);
    k_gemm<<<dim3(128 / 64, NG / 64), 256>>>(p_s1, fs2_w, fs2_b, p_z + 128,
                                             NG, 256, 128, 256, 1);
    k_gemm<<<dim3(1024 / 64, NG / 64), 256>>>(p_z, fc1_w, fc1_b, p_z1,
                                              NG, 256, 1024, 1024, 1);
    k_gemm<<<dim3(256 / 64, NG / 64), 256>>>(p_z1, fc2_w, fc2_b, p_z2,
                                             NG, 1024, 256, 256, 1);
    k_out<<<(NG * 32 + TB - 1) / TB, TB>>>(out_w, out_b, out);

    // restore zero state for next replay
    k_cleanup<<<(NN + TB - 1) / TB, TB>>>();
}